// round 14
// baseline (speedup 1.0000x reference)
#include <cuda_runtime.h>
#include <math.h>

// Diffusion: out = expm(-max(t,1e-8)*L) @ x, L = graph Laplacian (~32 nnz/row).
// Chebyshev expansion on [0, lambda_ub], fp32 sparse matvecs, ONE persistent
// kernel. R13 = R9 chassis (199us, best) + three low-risk deltas:
//   1. flag-array grid barrier: arrival = plain store to a per-block flag
//      (128 distinct addresses, no atomic serialization); wait = ONE warp
//      polling 4 coalesced flags/lane with nanosleep backoff.
//   2. software-pipelined ELL prefetch in the gather loop (LDS for batch k+1
//      issued during batch k's FFMAs).
//   3. float4-vectorized T_{j-2} smem buffer; tail tol 4e-5 (~1 fewer degree,
//      predicted rel_err ~3.4e-4 vs 1e-3 gate).

#define NN   2048
#define DD   512
#define ELLW 96           // max off-diag nnz per row (mean ~32, max ~60)
#define MMAX 48
#define RPB  16           // rows per block
#define TPR  64           // threads per row (8 channels each)
#define THREADS (RPB*TPR) // 1024
#define GRID (NN/RPB)     // 128 blocks -> 1 per SM

// -------- device-global scratch (no allocations allowed) --------
__device__ float        g_T1[NN * DD];
__device__ float        g_T2[NN * DD];
__device__ float        g_degv[NN];
__device__ float        g_bmax[GRID];
__device__ float        g_bmer[GRID];
__device__ float        g_bam [GRID];
__device__ volatile int g_flags[GRID];   // monotone generations, replay-safe

__device__ __forceinline__ float4 f4_load(const float* p) {
    return *reinterpret_cast<const float4*>(p);
}
__device__ __forceinline__ void f4_store(float* p, float4 v) {
    *reinterpret_cast<float4*>(p) = v;
}

// Flag barrier: arrival is a plain store (distinct address per block, no
// serialization); one warp polls all GRID flags coalesced, with backoff.
__device__ __forceinline__ void grid_barrier(int target) {
    __threadfence();
    __syncthreads();
    if (threadIdx.x == 0) g_flags[blockIdx.x] = target;
    if (threadIdx.x < 32) {
        for (;;) {
            int ok = 1;
#pragma unroll
            for (int k = 0; k < GRID / 32; k++)
                ok &= (g_flags[threadIdx.x + 32 * k] >= target) ? 1 : 0;
            if (__all_sync(0xffffffffu, ok)) break;
            __nanosleep(128);
        }
        __threadfence();
    }
    __syncthreads();
}

// ---------------------------------------------------------------------------
// SpMV core over channels {ch0..ch0+3} u {ch0+128..ch0+131}:
// batch-4 neighbors, 8 lane-contiguous LDG.128 in flight, with the next
// batch's ELL entries prefetched during the current batch's FFMAs.
// ---------------------------------------------------------------------------
__device__ __forceinline__ void spmv8(const float* __restrict__ Y, int ch0,
                                      const int2* __restrict__ sc,
                                      int cnt, float d,
                                      const float yk[8], float acc[8]) {
#pragma unroll
    for (int i = 0; i < 8; i++) acc[i] = d * yk[i];
    int k = 0;
    int2 e0, e1, e2, e3;
    if (k + 4 <= cnt) { e0 = sc[0]; e1 = sc[1]; e2 = sc[2]; e3 = sc[3]; }
    while (k + 4 <= cnt) {
        const float* p0 = Y + (e0.x << 9) + ch0;
        const float* p1 = Y + (e1.x << 9) + ch0;
        const float* p2 = Y + (e2.x << 9) + ch0;
        const float* p3 = Y + (e3.x << 9) + ch0;
        float4 a0 = f4_load(p0), a1 = f4_load(p0 + 128);
        float4 b0 = f4_load(p1), b1 = f4_load(p1 + 128);
        float4 c0 = f4_load(p2), c1 = f4_load(p2 + 128);
        float4 g0 = f4_load(p3), g1 = f4_load(p3 + 128);
        float v0 = __int_as_float(e0.y), v1 = __int_as_float(e1.y);
        float v2 = __int_as_float(e2.y), v3 = __int_as_float(e3.y);
        k += 4;
        if (k + 4 <= cnt) {        // prefetch next batch during FFMAs
            e0 = sc[k]; e1 = sc[k + 1]; e2 = sc[k + 2]; e3 = sc[k + 3];
        }
        acc[0] -= v0 * a0.x; acc[1] -= v0 * a0.y; acc[2] -= v0 * a0.z; acc[3] -= v0 * a0.w;
        acc[4] -= v0 * a1.x; acc[5] -= v0 * a1.y; acc[6] -= v0 * a1.z; acc[7] -= v0 * a1.w;
        acc[0] -= v1 * b0.x; acc[1] -= v1 * b0.y; acc[2] -= v1 * b0.z; acc[3] -= v1 * b0.w;
        acc[4] -= v1 * b1.x; acc[5] -= v1 * b1.y; acc[6] -= v1 * b1.z; acc[7] -= v1 * b1.w;
        acc[0] -= v2 * c0.x; acc[1] -= v2 * c0.y; acc[2] -= v2 * c0.z; acc[3] -= v2 * c0.w;
        acc[4] -= v2 * c1.x; acc[5] -= v2 * c1.y; acc[6] -= v2 * c1.z; acc[7] -= v2 * c1.w;
        acc[0] -= v3 * g0.x; acc[1] -= v3 * g0.y; acc[2] -= v3 * g0.z; acc[3] -= v3 * g0.w;
        acc[4] -= v3 * g1.x; acc[5] -= v3 * g1.y; acc[6] -= v3 * g1.z; acc[7] -= v3 * g1.w;
    }
    for (; k < cnt; k++) {
        int2 e = sc[k];
        float v = __int_as_float(e.y);
        const float* p = Y + (e.x << 9) + ch0;
        float4 a0 = f4_load(p), a1 = f4_load(p + 128);
        acc[0] -= v * a0.x; acc[1] -= v * a0.y; acc[2] -= v * a0.z; acc[3] -= v * a0.w;
        acc[4] -= v * a1.x; acc[5] -= v * a1.y; acc[6] -= v * a1.z; acc[7] -= v * a1.w;
    }
}

// ---------------------------------------------------------------------------
__global__ void __launch_bounds__(THREADS, 1)
cheb_all(const float* __restrict__ X, const float* __restrict__ L,
         const float* __restrict__ t_in, float* __restrict__ out) {
    const int tid  = threadIdx.x;
    const int rl   = tid >> 6;          // row within block (0..15)
    const int lane = tid & 63;          // thread within row (2 warps)
    const int row  = blockIdx.x * RPB + rl;
    const int wir  = lane >> 5;         // warp within row (0/1)

    __shared__ int2   s_ell[RPB][ELLW];
    __shared__ float4 s_ykm1[RPB][DD / 4];
    __shared__ float  s_diag[RPB];
    __shared__ int    s_cnt[RPB];
    __shared__ int    s_wt[RPB][2];
    __shared__ float  s_red[RPB][4];
    __shared__ float  s_coef[MMAX + 1];
    __shared__ float  s_a;
    __shared__ int    s_deg;
    __shared__ double s_c[MMAX + 1];

    const int bar_base = g_flags[blockIdx.x];   // persistent generation base
    int bar_num = 0;

    // ============ A) extract this block's 16 rows of dense L into smem ELL
    const float4* Lr4 = reinterpret_cast<const float4*>(L + (size_t)row * NN) + lane * 8;
    int   cnt = 0;
    float dv  = 0.f;
#pragma unroll
    for (int k = 0; k < 8; k++) {
        float4 v = Lr4[k];
        int c = lane * 32 + k * 4;
        if (c + 0 == row) dv = v.x; else cnt += (v.x != 0.f);
        if (c + 1 == row) dv = v.y; else cnt += (v.y != 0.f);
        if (c + 2 == row) dv = v.z; else cnt += (v.z != 0.f);
        if (c + 3 == row) dv = v.w; else cnt += (v.w != 0.f);
    }
    int inc = cnt;
#pragma unroll
    for (int off = 1; off < 32; off <<= 1) {
        int n = __shfl_up_sync(0xffffffffu, inc, off);
        if ((lane & 31) >= off) inc += n;
    }
    if ((lane & 31) == 31) s_wt[rl][wir] = inc;
    __syncthreads();
    int offset = inc - cnt + (wir ? s_wt[rl][0] : 0);
    int total  = s_wt[rl][0] + s_wt[rl][1];

    {   // pass 2: re-read (L1-hot) and compact into smem
        int o = offset;
#pragma unroll
        for (int k = 0; k < 8; k++) {
            float4 v = Lr4[k];
            int c = lane * 32 + k * 4;
            if (v.x != 0.f && c + 0 != row && o < ELLW) { s_ell[rl][o] = make_int2(c + 0, __float_as_int(-v.x)); o++; }
            if (v.y != 0.f && c + 1 != row && o < ELLW) { s_ell[rl][o] = make_int2(c + 1, __float_as_int(-v.y)); o++; }
            if (v.z != 0.f && c + 2 != row && o < ELLW) { s_ell[rl][o] = make_int2(c + 2, __float_as_int(-v.z)); o++; }
            if (v.w != 0.f && c + 3 != row && o < ELLW) { s_ell[rl][o] = make_int2(c + 3, __float_as_int(-v.w)); o++; }
        }
    }
    if (lane == (row >> 5)) s_diag[rl] = dv;
    if (lane == 0) s_cnt[rl] = (total < ELLW) ? total : ELLW;
    __syncthreads();

    if (lane == 0) g_degv[row] = s_diag[rl];
    if (tid == 0) {
        float m = s_diag[0];
#pragma unroll
        for (int i = 1; i < RPB; i++) m = fmaxf(m, s_diag[i]);
        g_bmax[blockIdx.x] = m;
    }

    // lane-contiguous channel layout: [ch0, ch0+3] and [ch0+128, ch0+131]
    const int   ch0   = wir * 256 + (lane & 31) * 4;
    const size_t ridx0 = (((size_t)row) << 9) + ch0;
    const size_t ridx1 = ridx0 + 128;
    const int   ci    = ch0 >> 2;               // float4 index; pair at ci+32

    float yk[8];
    {
        float4 xa = f4_load(X + ridx0), xb = f4_load(X + ridx1);
        yk[0] = xa.x; yk[1] = xa.y; yk[2] = xa.z; yk[3] = xa.w;
        yk[4] = xb.x; yk[5] = xb.y; yk[6] = xb.z; yk[7] = xb.w;
    }

    // ============ B) barrier 1: degree vector visible -> certified bounds
    grid_barrier(bar_base + (++bar_num));
    {
        const int rc = s_cnt[rl];
        float wsum = 0.f, dnbmax = 0.f;
        for (int k = lane; k < rc; k += TPR) {
            int2 e = s_ell[rl][k];
            float dn = g_degv[e.x];
            wsum  += __int_as_float(e.y) * dn;
            dnbmax = fmaxf(dnbmax, dn);
        }
#pragma unroll
        for (int off = 16; off; off >>= 1) {
            wsum  += __shfl_xor_sync(0xffffffffu, wsum, off);
            dnbmax = fmaxf(dnbmax, __shfl_xor_sync(0xffffffffu, dnbmax, off));
        }
        if ((lane & 31) == 0) {
            s_red[rl][wir]     = wsum;
            s_red[rl][2 + wir] = dnbmax;
        }
        __syncthreads();
        if (tid == 0) {
            float bm = 0.f, ba = 0.f;
#pragma unroll
            for (int i = 0; i < RPB; i++) {
                float du = s_diag[i];
                float ws = s_red[i][0] + s_red[i][1];
                float nm = fmaxf(s_red[i][2], s_red[i][3]);
                if (du > 1e-20f) bm = fmaxf(bm, du + ws / du);   // Merris
                ba = fmaxf(ba, du + nm);                          // Anderson-Morley
            }
            g_bmer[blockIdx.x] = bm;
            g_bam [blockIdx.x] = ba;
        }
    }

    // ============ C) barrier 2: bounds visible -> coefficients (warp 0)
    grid_barrier(bar_base + (++bar_num));
    if (tid < 32) {
        float dm = 0.f, mer = 0.f, am = 0.f;
        for (int i = tid; i < GRID; i += 32) {
            dm  = fmaxf(dm,  g_bmax[i]);
            mer = fmaxf(mer, g_bmer[i]);
            am  = fmaxf(am,  g_bam[i]);
        }
#pragma unroll
        for (int off = 16; off; off >>= 1) {
            dm  = fmaxf(dm,  __shfl_xor_sync(0xffffffffu, dm,  off));
            mer = fmaxf(mer, __shfl_xor_sync(0xffffffffu, mer, off));
            am  = fmaxf(am,  __shfl_xor_sync(0xffffffffu, am,  off));
        }
        double lub = 2.0 * (double)dm;                       // Gershgorin
        double b2  = (double)mer * 1.00001;
        double b3  = (double)am  * 1.00001;
        if (b2 > 1e-12 && b2 < lub) lub = b2;
        if (b3 > 1e-12 && b3 < lub) lub = b3;
        if (lub < 1e-12) lub = 1e-12;

        double tt = (double)fmaxf(t_in[0], 1e-8f);
        double z  = 0.5 * tt * lub;

        const double PI = 3.14159265358979323846;
        double th0 = PI * ((double)tid + 0.5) / 64.0;
        double th1 = PI * ((double)(tid + 32) + 0.5) / 64.0;
        double ct0 = cos(th0), ct1 = cos(th1);
        double f0 = exp(-z * (ct0 + 1.0));
        double f1 = exp(-z * (ct1 + 1.0));
        double cm2_0 = 1.0, cm1_0 = ct0, tc0 = 2.0 * ct0;
        double cm2_1 = 1.0, cm1_1 = ct1, tc1 = 2.0 * ct1;

        for (int k = 0; k <= MMAX; k++) {
            double ck0, ck1;
            if (k == 0)      { ck0 = 1.0; ck1 = 1.0; }
            else if (k == 1) { ck0 = ct0; ck1 = ct1; }
            else {
                ck0 = tc0 * cm1_0 - cm2_0;  cm2_0 = cm1_0;  cm1_0 = ck0;
                ck1 = tc1 * cm1_1 - cm2_1;  cm2_1 = cm1_1;  cm1_1 = ck1;
            }
            double p = f0 * ck0 + f1 * ck1;
#pragma unroll
            for (int off = 16; off; off >>= 1)
                p += __shfl_xor_sync(0xffffffffu, p, off);
            if (tid == 0) {
                double c = (2.0 / 64.0) * p;
                if (k == 0) c *= 0.5;
                s_c[k] = c;
            }
        }
        __syncwarp();
        if (tid == 0) {
            double tail = 0.0;
            int deg = 2;
            for (int k = MMAX; k >= 2; k--) {
                tail += fabs(s_c[k]);
                if (tail > 4e-5) { deg = k; break; }
            }
            if (deg > MMAX) deg = MMAX;
            s_deg = deg;
            s_a   = (float)(4.0 / lub);
            for (int k = 0; k <= MMAX; k++) s_coef[k] = (float)s_c[k];
        }
    }
    __syncthreads();

    // ============ D) Chebyshev recurrence
    const float d    = s_diag[rl];
    const float a    = s_a;          // 4/lub
    const int   deg  = s_deg;        // identical across all blocks
    const int   cnt8 = s_cnt[rl];

    float acc[8], o[8];

    // T1 = (2/lub)*L@x - x ;  out = c0*x + c1*T1
    spmv8(X, ch0, s_ell[rl], cnt8, d, yk, acc);
    {
        const float ha = 0.5f * a;
        const float c0 = s_coef[0], c1 = s_coef[1];
        float4 pA, pB;
#pragma unroll
        for (int i = 0; i < 8; i++) {
            float t1 = ha * acc[i] - yk[i];
            o[i] = c0 * yk[i] + c1 * t1;
            if (i < 4) (&pA.x)[i] = yk[i]; else (&pB.x)[i - 4] = yk[i];
            yk[i] = t1;
        }
        s_ykm1[rl][ci]      = pA;   // T0
        s_ykm1[rl][ci + 32] = pB;
        float4 va = {yk[0], yk[1], yk[2], yk[3]};
        float4 vb = {yk[4], yk[5], yk[6], yk[7]};
        f4_store(g_T1 + ridx0, va);
        f4_store(g_T1 + ridx1, vb);
    }

    for (int j = 2; j <= deg; j++) {
        grid_barrier(bar_base + (++bar_num));     // T_{j-1} globally visible
        const float* Tp = (j & 1) ? g_T2 : g_T1;
        float*       Tc = (j & 1) ? g_T1 : g_T2;

        spmv8(Tp, ch0, s_ell[rl], cnt8, d, yk, acc);

        const float c = s_coef[j];
        float4 mA = s_ykm1[rl][ci];
        float4 mB = s_ykm1[rl][ci + 32];
        float4 pA, pB, tA, tB;
#pragma unroll
        for (int i = 0; i < 8; i++) {
            float m  = (i < 4) ? (&mA.x)[i] : (&mB.x)[i - 4];
            float tn = a * acc[i] - 2.f * yk[i] - m;
            o[i] += c * tn;
            if (i < 4) { (&pA.x)[i] = yk[i];     (&tA.x)[i] = tn; }
            else       { (&pB.x)[i - 4] = yk[i]; (&tB.x)[i - 4] = tn; }
            yk[i] = tn;
        }
        s_ykm1[rl][ci]      = pA;
        s_ykm1[rl][ci + 32] = pB;
        if (j < deg) {                            // last T never gathered
            f4_store(Tc + ridx0, tA);
            f4_store(Tc + ridx1, tB);
        }
    }

    float4 oa = {o[0], o[1], o[2], o[3]};
    float4 ob = {o[4], o[5], o[6], o[7]};
    f4_store(out + ridx0, oa);
    f4_store(out + ridx1, ob);
}

// ---------------------------------------------------------------------------
extern "C" void kernel_launch(void* const* d_in, const int* in_sizes, int n_in,
                              void* d_out, int out_size) {
    const float* x = nullptr;
    const float* L = nullptr;
    const float* t = nullptr;
    for (int i = 0; i < n_in; i++) {
        if      (in_sizes[i] == NN * DD) x = (const float*)d_in[i];
        else if (in_sizes[i] == NN * NN) L = (const float*)d_in[i];
        else if (in_sizes[i] == 1)       t = (const float*)d_in[i];
    }
    float* out = (float*)d_out;

    cheb_all<<<GRID, THREADS>>>(x, L, t, out);
}

// round 15
// speedup vs baseline: 1.4649x; 1.4649x over previous
#include <cuda_runtime.h>
#include <math.h>

// Diffusion: out = expm(-max(t,1e-8)*L) @ x, L = graph Laplacian (~32 nnz/row).
// Chebyshev expansion of e^{-t*lambda} on [0, lambda_ub], fp32 sparse matvecs,
// ONE persistent kernel. R14 = EXACT R9 chassis (best, 199us):
//   - central-atomic grid barrier, one poller/block + nanosleep (twice proven;
//     flag-array variants regressed in R6 AND R13 -> permanently rejected)
//   - lane-contiguous channel layout (each LDG/STG.128 = 512B warp segment)
//   - plain batch-4 gather loop (no ELL prefetch rotation -- R13 regressed)
// Single delta vs R9: Chebyshev tail tolerance 2e-5 -> 4e-5 (R14 measured
// rel_err 5.49e-4 < 1e-3 with this tolerance; saves 1-2 matvec iterations).

#define NN   2048
#define DD   512
#define ELLW 96           // max off-diag nnz per row (mean ~32, max ~60)
#define MMAX 48
#define RPB  16           // rows per block
#define TPR  64           // threads per row (8 channels each)
#define THREADS (RPB*TPR) // 1024
#define GRID (NN/RPB)     // 128 blocks -> 1 per SM

// -------- device-global scratch (no allocations allowed) --------
__device__ float g_T1[NN * DD];
__device__ float g_T2[NN * DD];
__device__ float g_degv[NN];
__device__ float g_bmax[GRID];
__device__ float g_bmer[GRID];
__device__ float g_bam [GRID];

__device__ int          g_bar_count = 0;
__device__ volatile int g_bar_gen   = 0;

__device__ __forceinline__ float4 f4_load(const float* p) {
    return *reinterpret_cast<const float4*>(p);
}
__device__ __forceinline__ void f4_store(float* p, float4 v) {
    *reinterpret_cast<float4*>(p) = v;
}

__device__ __forceinline__ void grid_barrier() {
    __threadfence();
    __syncthreads();
    if (threadIdx.x == 0) {
        int gen = g_bar_gen;
        if (atomicAdd(&g_bar_count, 1) == GRID - 1) {
            g_bar_count = 0;
            __threadfence();
            g_bar_gen = gen + 1;
        } else {
            while (g_bar_gen == gen) __nanosleep(64);
        }
        __threadfence();
    }
    __syncthreads();
}

// ---------------------------------------------------------------------------
// SpMV core over channels {ch0..ch0+3} u {ch0+128..ch0+131}:
// acc[0..7] = d*yk - sum_j val_j * Y[col_j, ...]; batch-4 neighbors,
// 8 independent lane-contiguous LDG.128 in flight.
// ---------------------------------------------------------------------------
__device__ __forceinline__ void spmv8(const float* __restrict__ Y, int ch0,
                                      const int2* __restrict__ se,
                                      int cnt, float d,
                                      const float yk[8], float acc[8]) {
#pragma unroll
    for (int i = 0; i < 8; i++) acc[i] = d * yk[i];
    int k = 0;
    for (; k + 4 <= cnt; k += 4) {
        int2 e0 = se[k], e1 = se[k + 1], e2 = se[k + 2], e3 = se[k + 3];
        const float* p0 = Y + (((size_t)e0.x) << 9) + ch0;
        const float* p1 = Y + (((size_t)e1.x) << 9) + ch0;
        const float* p2 = Y + (((size_t)e2.x) << 9) + ch0;
        const float* p3 = Y + (((size_t)e3.x) << 9) + ch0;
        float4 a0 = f4_load(p0), a1 = f4_load(p0 + 128);
        float4 b0 = f4_load(p1), b1 = f4_load(p1 + 128);
        float4 c0 = f4_load(p2), c1 = f4_load(p2 + 128);
        float4 g0 = f4_load(p3), g1 = f4_load(p3 + 128);
        float v0 = __int_as_float(e0.y), v1 = __int_as_float(e1.y);
        float v2 = __int_as_float(e2.y), v3 = __int_as_float(e3.y);
        acc[0] -= v0 * a0.x; acc[1] -= v0 * a0.y; acc[2] -= v0 * a0.z; acc[3] -= v0 * a0.w;
        acc[4] -= v0 * a1.x; acc[5] -= v0 * a1.y; acc[6] -= v0 * a1.z; acc[7] -= v0 * a1.w;
        acc[0] -= v1 * b0.x; acc[1] -= v1 * b0.y; acc[2] -= v1 * b0.z; acc[3] -= v1 * b0.w;
        acc[4] -= v1 * b1.x; acc[5] -= v1 * b1.y; acc[6] -= v1 * b1.z; acc[7] -= v1 * b1.w;
        acc[0] -= v2 * c0.x; acc[1] -= v2 * c0.y; acc[2] -= v2 * c0.z; acc[3] -= v2 * c0.w;
        acc[4] -= v2 * c1.x; acc[5] -= v2 * c1.y; acc[6] -= v2 * c1.z; acc[7] -= v2 * c1.w;
        acc[0] -= v3 * g0.x; acc[1] -= v3 * g0.y; acc[2] -= v3 * g0.z; acc[3] -= v3 * g0.w;
        acc[4] -= v3 * g1.x; acc[5] -= v3 * g1.y; acc[6] -= v3 * g1.z; acc[7] -= v3 * g1.w;
    }
    for (; k < cnt; k++) {
        int2 e0 = se[k];
        float v0 = __int_as_float(e0.y);
        const float* p0 = Y + (((size_t)e0.x) << 9) + ch0;
        float4 a0 = f4_load(p0), a1 = f4_load(p0 + 128);
        acc[0] -= v0 * a0.x; acc[1] -= v0 * a0.y; acc[2] -= v0 * a0.z; acc[3] -= v0 * a0.w;
        acc[4] -= v0 * a1.x; acc[5] -= v0 * a1.y; acc[6] -= v0 * a1.z; acc[7] -= v0 * a1.w;
    }
}

// ---------------------------------------------------------------------------
__global__ void __launch_bounds__(THREADS, 1)
cheb_all(const float* __restrict__ X, const float* __restrict__ L,
         const float* __restrict__ t_in, float* __restrict__ out) {
    const int tid  = threadIdx.x;
    const int rl   = tid >> 6;          // row within block (0..15)
    const int lane = tid & 63;          // thread within row (2 warps)
    const int row  = blockIdx.x * RPB + rl;
    const int wir  = lane >> 5;         // warp within row (0/1)

    __shared__ int2   s_ell[RPB][ELLW];
    __shared__ float  s_ykm1[RPB][DD];
    __shared__ float  s_diag[RPB];
    __shared__ int    s_cnt[RPB];
    __shared__ int    s_wt[RPB][2];
    __shared__ float  s_red[RPB][4];
    __shared__ float  s_coef[MMAX + 1];
    __shared__ float  s_a;
    __shared__ int    s_deg;
    __shared__ double s_c[MMAX + 1];

    // ============ A) extract this block's 16 rows of dense L into smem ELL
    const float4* Lr4 = reinterpret_cast<const float4*>(L + (size_t)row * NN) + lane * 8;
    int   cnt = 0;
    float dv  = 0.f;
#pragma unroll
    for (int k = 0; k < 8; k++) {
        float4 v = Lr4[k];
        int c = lane * 32 + k * 4;
        if (c + 0 == row) dv = v.x; else cnt += (v.x != 0.f);
        if (c + 1 == row) dv = v.y; else cnt += (v.y != 0.f);
        if (c + 2 == row) dv = v.z; else cnt += (v.z != 0.f);
        if (c + 3 == row) dv = v.w; else cnt += (v.w != 0.f);
    }
    int inc = cnt;
#pragma unroll
    for (int off = 1; off < 32; off <<= 1) {
        int n = __shfl_up_sync(0xffffffffu, inc, off);
        if ((lane & 31) >= off) inc += n;
    }
    if ((lane & 31) == 31) s_wt[rl][wir] = inc;
    __syncthreads();
    int offset = inc - cnt + (wir ? s_wt[rl][0] : 0);
    int total  = s_wt[rl][0] + s_wt[rl][1];

    {   // pass 2: re-read (L1-hot) and compact into smem
        int o = offset;
#pragma unroll
        for (int k = 0; k < 8; k++) {
            float4 v = Lr4[k];
            int c = lane * 32 + k * 4;
            if (v.x != 0.f && c + 0 != row && o < ELLW) { s_ell[rl][o] = make_int2(c + 0, __float_as_int(-v.x)); o++; }
            if (v.y != 0.f && c + 1 != row && o < ELLW) { s_ell[rl][o] = make_int2(c + 1, __float_as_int(-v.y)); o++; }
            if (v.z != 0.f && c + 2 != row && o < ELLW) { s_ell[rl][o] = make_int2(c + 2, __float_as_int(-v.z)); o++; }
            if (v.w != 0.f && c + 3 != row && o < ELLW) { s_ell[rl][o] = make_int2(c + 3, __float_as_int(-v.w)); o++; }
        }
    }
    if (lane == (row >> 5)) s_diag[rl] = dv;
    if (lane == 0) s_cnt[rl] = (total < ELLW) ? total : ELLW;
    __syncthreads();

    if (lane == 0) g_degv[row] = s_diag[rl];
    if (tid == 0) {
        float m = s_diag[0];
#pragma unroll
        for (int i = 1; i < RPB; i++) m = fmaxf(m, s_diag[i]);
        g_bmax[blockIdx.x] = m;
    }

    // lane-contiguous channel layout: [ch0, ch0+3] and [ch0+128, ch0+131]
    const int   ch0   = wir * 256 + (lane & 31) * 4;
    const size_t ridx0 = (((size_t)row) << 9) + ch0;
    const size_t ridx1 = ridx0 + 128;

    float yk[8];
    {
        float4 xa = f4_load(X + ridx0), xb = f4_load(X + ridx1);
        yk[0] = xa.x; yk[1] = xa.y; yk[2] = xa.z; yk[3] = xa.w;
        yk[4] = xb.x; yk[5] = xb.y; yk[6] = xb.z; yk[7] = xb.w;
    }

    // ============ B) barrier 1: degree vector visible -> certified bounds
    grid_barrier();
    {
        const int rc = s_cnt[rl];
        float wsum = 0.f, dnbmax = 0.f;
        for (int k = lane; k < rc; k += TPR) {
            int2 e = s_ell[rl][k];
            float dn = g_degv[e.x];
            wsum  += __int_as_float(e.y) * dn;
            dnbmax = fmaxf(dnbmax, dn);
        }
#pragma unroll
        for (int off = 16; off; off >>= 1) {
            wsum  += __shfl_xor_sync(0xffffffffu, wsum, off);
            dnbmax = fmaxf(dnbmax, __shfl_xor_sync(0xffffffffu, dnbmax, off));
        }
        if ((lane & 31) == 0) {
            s_red[rl][wir]     = wsum;
            s_red[rl][2 + wir] = dnbmax;
        }
        __syncthreads();
        if (tid == 0) {
            float bm = 0.f, ba = 0.f;
#pragma unroll
            for (int i = 0; i < RPB; i++) {
                float du = s_diag[i];
                float ws = s_red[i][0] + s_red[i][1];
                float nm = fmaxf(s_red[i][2], s_red[i][3]);
                if (du > 1e-20f) bm = fmaxf(bm, du + ws / du);   // Merris
                ba = fmaxf(ba, du + nm);                          // Anderson-Morley
            }
            g_bmer[blockIdx.x] = bm;
            g_bam [blockIdx.x] = ba;
        }
    }

    // ============ C) barrier 2: bounds visible -> coefficients (warp 0)
    grid_barrier();
    if (tid < 32) {
        float dm = 0.f, mer = 0.f, am = 0.f;
        for (int i = tid; i < GRID; i += 32) {
            dm  = fmaxf(dm,  g_bmax[i]);
            mer = fmaxf(mer, g_bmer[i]);
            am  = fmaxf(am,  g_bam[i]);
        }
#pragma unroll
        for (int off = 16; off; off >>= 1) {
            dm  = fmaxf(dm,  __shfl_xor_sync(0xffffffffu, dm,  off));
            mer = fmaxf(mer, __shfl_xor_sync(0xffffffffu, mer, off));
            am  = fmaxf(am,  __shfl_xor_sync(0xffffffffu, am,  off));
        }
        double lub = 2.0 * (double)dm;                       // Gershgorin
        double b2  = (double)mer * 1.00001;
        double b3  = (double)am  * 1.00001;
        if (b2 > 1e-12 && b2 < lub) lub = b2;
        if (b3 > 1e-12 && b3 < lub) lub = b3;
        if (lub < 1e-12) lub = 1e-12;

        double tt = (double)fmaxf(t_in[0], 1e-8f);
        double z  = 0.5 * tt * lub;

        const double PI = 3.14159265358979323846;
        double th0 = PI * ((double)tid + 0.5) / 64.0;
        double th1 = PI * ((double)(tid + 32) + 0.5) / 64.0;
        double ct0 = cos(th0), ct1 = cos(th1);
        double f0 = exp(-z * (ct0 + 1.0));
        double f1 = exp(-z * (ct1 + 1.0));
        double cm2_0 = 1.0, cm1_0 = ct0, tc0 = 2.0 * ct0;
        double cm2_1 = 1.0, cm1_1 = ct1, tc1 = 2.0 * ct1;

        for (int k = 0; k <= MMAX; k++) {
            double ck0, ck1;
            if (k == 0)      { ck0 = 1.0; ck1 = 1.0; }
            else if (k == 1) { ck0 = ct0; ck1 = ct1; }
            else {
                ck0 = tc0 * cm1_0 - cm2_0;  cm2_0 = cm1_0;  cm1_0 = ck0;
                ck1 = tc1 * cm1_1 - cm2_1;  cm2_1 = cm1_1;  cm1_1 = ck1;
            }
            double p = f0 * ck0 + f1 * ck1;
#pragma unroll
            for (int off = 16; off; off >>= 1)
                p += __shfl_xor_sync(0xffffffffu, p, off);
            if (tid == 0) {
                double c = (2.0 / 64.0) * p;
                if (k == 0) c *= 0.5;
                s_c[k] = c;
            }
        }
        __syncwarp();
        if (tid == 0) {
            double tail = 0.0;
            int deg = 2;
            for (int k = MMAX; k >= 2; k--) {
                tail += fabs(s_c[k]);
                if (tail > 4e-5) { deg = k; break; }   // R14-verified: rel_err 5.49e-4
            }
            if (deg > MMAX) deg = MMAX;
            s_deg = deg;
            s_a   = (float)(4.0 / lub);
            for (int k = 0; k <= MMAX; k++) s_coef[k] = (float)s_c[k];
        }
    }
    __syncthreads();

    // ============ D) Chebyshev recurrence
    const float d    = s_diag[rl];
    const float a    = s_a;          // 4/lub
    const int   deg  = s_deg;
    const int   cnt8 = s_cnt[rl];

    float acc[8], o[8];

    // T1 = (2/lub)*L@x - x ;  out = c0*x + c1*T1
    spmv8(X, ch0, s_ell[rl], cnt8, d, yk, acc);
    {
        const float ha = 0.5f * a;
        const float c0 = s_coef[0], c1 = s_coef[1];
#pragma unroll
        for (int i = 0; i < 8; i++) {
            float t1 = ha * acc[i] - yk[i];
            o[i] = c0 * yk[i] + c1 * t1;
            int c = ch0 + ((i < 4) ? i : (124 + i));  // i>=4 -> ch0+128+(i-4)
            s_ykm1[rl][c] = yk[i];    // T0
            yk[i] = t1;               // T1
        }
        float4 va = {yk[0], yk[1], yk[2], yk[3]};
        float4 vb = {yk[4], yk[5], yk[6], yk[7]};
        f4_store(g_T1 + ridx0, va);
        f4_store(g_T1 + ridx1, vb);
    }

    for (int j = 2; j <= deg; j++) {
        grid_barrier();                           // T_{j-1} globally visible
        const float* Tp = (j & 1) ? g_T2 : g_T1;
        float*       Tc = (j & 1) ? g_T1 : g_T2;

        spmv8(Tp, ch0, s_ell[rl], cnt8, d, yk, acc);

        const float c = s_coef[j];
        float tn[8];
#pragma unroll
        for (int i = 0; i < 8; i++) {
            int cc = ch0 + ((i < 4) ? i : (124 + i));
            tn[i] = a * acc[i] - 2.f * yk[i] - s_ykm1[rl][cc];
            o[i] += c * tn[i];
            s_ykm1[rl][cc] = yk[i];
            yk[i] = tn[i];
        }
        if (j < deg) {                            // last T never gathered
            float4 va = {tn[0], tn[1], tn[2], tn[3]};
            float4 vb = {tn[4], tn[5], tn[6], tn[7]};
            f4_store(Tc + ridx0, va);
            f4_store(Tc + ridx1, vb);
        }
    }

    float4 oa = {o[0], o[1], o[2], o[3]};
    float4 ob = {o[4], o[5], o[6], o[7]};
    f4_store(out + ridx0, oa);
    f4_store(out + ridx1, ob);
}

// ---------------------------------------------------------------------------
extern "C" void kernel_launch(void* const* d_in, const int* in_sizes, int n_in,
                              void* d_out, int out_size) {
    const float* x = nullptr;
    const float* L = nullptr;
    const float* t = nullptr;
    for (int i = 0; i < n_in; i++) {
        if      (in_sizes[i] == NN * DD) x = (const float*)d_in[i];
        else if (in_sizes[i] == NN * NN) L = (const float*)d_in[i];
        else if (in_sizes[i] == 1)       t = (const float*)d_in[i];
    }
    float* out = (float*)d_out;

    cheb_all<<<GRID, THREADS>>>(x, L, t, out);
}

// round 16
// speedup vs baseline: 1.4971x; 1.0220x over previous
#include <cuda_runtime.h>
#include <math.h>

// Diffusion: out = expm(-max(t,1e-8)*L) @ x, L = graph Laplacian (~32 nnz/row).
// Chebyshev on [0, lambda_ub], fp32 sparse matvecs, ONE persistent kernel.
// R15: half-list split + partner exchange to kill global max-row skew.
//   Rows counting-sorted by nnz (R10-proven). Block b owns ranks
//   {b*8+i} u {2047-b*8-i}: 8 min-max pairs, 16 groups of 64 threads.
//   Each group (8 ch/thread, UNCHANGED batch-4 spmv8) gathers:
//     sub-loop 1: second half of its PARTNER row's list (d=0) -> smem partial
//     sub-loop 2: first half of its OWN row (with diagonal)
//   then combines after the existing __syncthreads. Every group's trip count
//   = (c_q + c_{2047-q})/2 ~ 31 uniformly (was max 58) -> barriers no longer
//   wait on the heaviest row. o accumulator moved to smem (register budget).
//   Central-atomic barrier (proven), Merris/AM/Gershgorin bounds, tol 4e-5.

#define NN   2048
#define DD   512
#define ELLW 96
#define MMAX 48
#define THREADS 1024
#define GRID 128          // 1 block/SM
#define NB   97           // histogram bins: cnt in [0, 96]

// dynamic smem layout (bytes)
#define SZ_ELL   (16 * ELLW * 8)          // int2 s_ell[16][ELLW]   = 12288
#define SZ_ROWF  (16 * DD * 4)            // float [16][512]        = 32768
#define OFF_ELL   0
#define OFF_YKM1 (OFF_ELL + SZ_ELL)
#define OFF_PART (OFF_YKM1 + SZ_ROWF)
#define OFF_O    (OFF_PART + SZ_ROWF)
#define SMEM_DYN (OFF_O + SZ_ROWF)        // 110592 bytes

// -------- device-global scratch (no allocations allowed) --------
__device__ float g_T1[NN * DD];
__device__ float g_T2[NN * DD];
__device__ int2  g_ell[NN * ELLW];
__device__ float g_diag[NN];
__device__ int   g_cnt[NN];
__device__ int   g_hist[NB];
__device__ int   g_offs[NB];
__device__ int   g_perm[NN];
__device__ float g_bmax[GRID];
__device__ float g_bmer[GRID];
__device__ float g_bam [GRID];

__device__ int          g_bar_count = 0;
__device__ volatile int g_bar_gen   = 0;

__device__ __forceinline__ float4 f4_load(const float* p) {
    return *reinterpret_cast<const float4*>(p);
}
__device__ __forceinline__ void f4_store(float* p, float4 v) {
    *reinterpret_cast<float4*>(p) = v;
}

__device__ __forceinline__ void grid_barrier() {
    __threadfence();
    __syncthreads();
    if (threadIdx.x == 0) {
        int gen = g_bar_gen;
        if (atomicAdd(&g_bar_count, 1) == GRID - 1) {
            g_bar_count = 0;
            __threadfence();
            g_bar_gen = gen + 1;
        } else {
            while (g_bar_gen == gen) __nanosleep(64);
        }
        __threadfence();
    }
    __syncthreads();
}

// ---------------------------------------------------------------------------
// UNCHANGED R9 SpMV core: acc[0..7] = d*yk - sum val_j * Y[col_j, ...]
// batch-4 neighbors, 8 lane-contiguous LDG.128 in flight.
// ---------------------------------------------------------------------------
__device__ __forceinline__ void spmv8(const float* __restrict__ Y, int ch0,
                                      const int2* __restrict__ se,
                                      int cnt, float d,
                                      const float yk[8], float acc[8]) {
#pragma unroll
    for (int i = 0; i < 8; i++) acc[i] = d * yk[i];
    int k = 0;
    for (; k + 4 <= cnt; k += 4) {
        int2 e0 = se[k], e1 = se[k + 1], e2 = se[k + 2], e3 = se[k + 3];
        const float* p0 = Y + (((size_t)e0.x) << 9) + ch0;
        const float* p1 = Y + (((size_t)e1.x) << 9) + ch0;
        const float* p2 = Y + (((size_t)e2.x) << 9) + ch0;
        const float* p3 = Y + (((size_t)e3.x) << 9) + ch0;
        float4 a0 = f4_load(p0), a1 = f4_load(p0 + 128);
        float4 b0 = f4_load(p1), b1 = f4_load(p1 + 128);
        float4 c0 = f4_load(p2), c1 = f4_load(p2 + 128);
        float4 g0 = f4_load(p3), g1 = f4_load(p3 + 128);
        float v0 = __int_as_float(e0.y), v1 = __int_as_float(e1.y);
        float v2 = __int_as_float(e2.y), v3 = __int_as_float(e3.y);
        acc[0] -= v0 * a0.x; acc[1] -= v0 * a0.y; acc[2] -= v0 * a0.z; acc[3] -= v0 * a0.w;
        acc[4] -= v0 * a1.x; acc[5] -= v0 * a1.y; acc[6] -= v0 * a1.z; acc[7] -= v0 * a1.w;
        acc[0] -= v1 * b0.x; acc[1] -= v1 * b0.y; acc[2] -= v1 * b0.z; acc[3] -= v1 * b0.w;
        acc[4] -= v1 * b1.x; acc[5] -= v1 * b1.y; acc[6] -= v1 * b1.z; acc[7] -= v1 * b1.w;
        acc[0] -= v2 * c0.x; acc[1] -= v2 * c0.y; acc[2] -= v2 * c0.z; acc[3] -= v2 * c0.w;
        acc[4] -= v2 * c1.x; acc[5] -= v2 * c1.y; acc[6] -= v2 * c1.z; acc[7] -= v2 * c1.w;
        acc[0] -= v3 * g0.x; acc[1] -= v3 * g0.y; acc[2] -= v3 * g0.z; acc[3] -= v3 * g0.w;
        acc[4] -= v3 * g1.x; acc[5] -= v3 * g1.y; acc[6] -= v3 * g1.z; acc[7] -= v3 * g1.w;
    }
    for (; k < cnt; k++) {
        int2 e0 = se[k];
        float v0 = __int_as_float(e0.y);
        const float* p0 = Y + (((size_t)e0.x) << 9) + ch0;
        float4 a0 = f4_load(p0), a1 = f4_load(p0 + 128);
        acc[0] -= v0 * a0.x; acc[1] -= v0 * a0.y; acc[2] -= v0 * a0.z; acc[3] -= v0 * a0.w;
        acc[4] -= v0 * a1.x; acc[5] -= v0 * a1.y; acc[6] -= v0 * a1.z; acc[7] -= v0 * a1.w;
    }
}

// ---------------------------------------------------------------------------
__global__ void __launch_bounds__(THREADS, 1)
cheb_all(const float* __restrict__ X, const float* __restrict__ L,
         const float* __restrict__ t_in, float* __restrict__ out) {
    extern __shared__ char dyn[];
    const int tid = threadIdx.x;
    const int blk = blockIdx.x;

    // small static shared
    __shared__ float  s_diagE[16];
    __shared__ int    s_cntE[16];
    __shared__ int    s_wt[16][2];
    __shared__ float  s_red[16][4];
    __shared__ int    s_scan[128];
    __shared__ float  s_coef[MMAX + 1];
    __shared__ float  s_a;
    __shared__ int    s_deg;
    __shared__ double s_c[MMAX + 1];
    __shared__ float  s_diagG[16];
    __shared__ int    s_cntG[16];

    // extraction view: 16 own rows (blk*16+rl), 64 threads each
    const int rl   = tid >> 6;
    const int lane = tid & 63;
    const int wir  = lane >> 5;
    const int erow = blk * 16 + rl;

    if (tid < NB) g_hist[tid] = 0;   // all blocks write 0 before B0: benign

    // ============ A) extract own 16 rows of dense L -> GLOBAL ELL
    const float4* Lr4 = reinterpret_cast<const float4*>(L + (size_t)erow * NN) + lane * 8;
    int   cnt = 0;
    float dv  = 0.f;
#pragma unroll
    for (int k = 0; k < 8; k++) {
        float4 v = Lr4[k];
        int c = lane * 32 + k * 4;
        if (c + 0 == erow) dv = v.x; else cnt += (v.x != 0.f);
        if (c + 1 == erow) dv = v.y; else cnt += (v.y != 0.f);
        if (c + 2 == erow) dv = v.z; else cnt += (v.z != 0.f);
        if (c + 3 == erow) dv = v.w; else cnt += (v.w != 0.f);
    }
    int inc = cnt;
#pragma unroll
    for (int off = 1; off < 32; off <<= 1) {
        int n = __shfl_up_sync(0xffffffffu, inc, off);
        if ((lane & 31) >= off) inc += n;
    }
    if ((lane & 31) == 31) s_wt[rl][wir] = inc;
    __syncthreads();
    int offset = inc - cnt + (wir ? s_wt[rl][0] : 0);
    int total  = s_wt[rl][0] + s_wt[rl][1];
    {
        int o = offset;
        int2* er = g_ell + (size_t)erow * ELLW;
#pragma unroll
        for (int k = 0; k < 8; k++) {
            float4 v = Lr4[k];
            int c = lane * 32 + k * 4;
            if (v.x != 0.f && c + 0 != erow && o < ELLW) { er[o] = make_int2(c + 0, __float_as_int(-v.x)); o++; }
            if (v.y != 0.f && c + 1 != erow && o < ELLW) { er[o] = make_int2(c + 1, __float_as_int(-v.y)); o++; }
            if (v.z != 0.f && c + 2 != erow && o < ELLW) { er[o] = make_int2(c + 2, __float_as_int(-v.z)); o++; }
            if (v.w != 0.f && c + 3 != erow && o < ELLW) { er[o] = make_int2(c + 3, __float_as_int(-v.w)); o++; }
        }
    }
    if (lane == (erow >> 5)) s_diagE[rl] = dv;
    if (lane == 0) s_cntE[rl] = (total < ELLW) ? total : ELLW;
    __syncthreads();

    if (lane == 0) {
        g_diag[erow] = s_diagE[rl];
        g_cnt[erow]  = s_cntE[rl];
    }
    if (tid == 0) {
        float m = s_diagE[0];
#pragma unroll
        for (int i = 1; i < 16; i++) m = fmaxf(m, s_diagE[i]);
        g_bmax[blk] = m;
    }

    // ============ B0: ELL/diag/cnt/hist-zero visible
    grid_barrier();

    // bounds partials + histogram
    {
        const int rc = s_cntE[rl];
        float wsum = 0.f, dnb = 0.f;
        const int2* er = g_ell + (size_t)erow * ELLW;
        for (int k = lane; k < rc; k += 64) {
            int2 e = er[k];
            float dn = g_diag[e.x];
            wsum += __int_as_float(e.y) * dn;
            dnb   = fmaxf(dnb, dn);
        }
#pragma unroll
        for (int off = 16; off; off >>= 1) {
            wsum += __shfl_xor_sync(0xffffffffu, wsum, off);
            dnb   = fmaxf(dnb, __shfl_xor_sync(0xffffffffu, dnb, off));
        }
        if ((lane & 31) == 0) {
            s_red[rl][wir]     = wsum;
            s_red[rl][2 + wir] = dnb;
        }
        if (lane == 0) atomicAdd(&g_hist[rc], 1);
        __syncthreads();
        if (tid == 0) {
            float bm = 0.f, ba = 0.f;
#pragma unroll
            for (int i = 0; i < 16; i++) {
                float du = s_diagE[i];
                float ws = s_red[i][0] + s_red[i][1];
                float nm = fmaxf(s_red[i][2], s_red[i][3]);
                if (du > 1e-20f) bm = fmaxf(bm, du + ws / du);   // Merris
                ba = fmaxf(ba, du + nm);                          // Anderson-Morley
            }
            g_bmer[blk] = bm;
            g_bam [blk] = ba;
        }
    }

    // ============ B1: hist + bounds visible
    grid_barrier();

    // block 0: exclusive prefix of histogram -> g_offs
    if (blk == 0) {
        if (tid < 128) s_scan[tid] = (tid < NB) ? g_hist[tid] : 0;
        __syncthreads();
        for (int off = 1; off < 128; off <<= 1) {
            int v = 0;
            if (tid < 128 && tid >= off) v = s_scan[tid - off];
            __syncthreads();
            if (tid < 128) s_scan[tid] += v;
            __syncthreads();
        }
        if (tid < NB) g_offs[tid] = s_scan[tid] - g_hist[tid];
    }

    // coefficients (every block redundantly; warp 0)
    if (tid < 32) {
        float dm = 0.f, mer = 0.f, am = 0.f;
        for (int i = tid; i < GRID; i += 32) {
            dm  = fmaxf(dm,  g_bmax[i]);
            mer = fmaxf(mer, g_bmer[i]);
            am  = fmaxf(am,  g_bam[i]);
        }
#pragma unroll
        for (int off = 16; off; off >>= 1) {
            dm  = fmaxf(dm,  __shfl_xor_sync(0xffffffffu, dm,  off));
            mer = fmaxf(mer, __shfl_xor_sync(0xffffffffu, mer, off));
            am  = fmaxf(am,  __shfl_xor_sync(0xffffffffu, am,  off));
        }
        double lub = 2.0 * (double)dm;                       // Gershgorin
        double b2  = (double)mer * 1.00001;
        double b3  = (double)am  * 1.00001;
        if (b2 > 1e-12 && b2 < lub) lub = b2;
        if (b3 > 1e-12 && b3 < lub) lub = b3;
        if (lub < 1e-12) lub = 1e-12;

        double tt = (double)fmaxf(t_in[0], 1e-8f);
        double z  = 0.5 * tt * lub;

        const double PI = 3.14159265358979323846;
        double th0 = PI * ((double)tid + 0.5) / 64.0;
        double th1 = PI * ((double)(tid + 32) + 0.5) / 64.0;
        double ct0 = cos(th0), ct1 = cos(th1);
        double f0 = exp(-z * (ct0 + 1.0));
        double f1 = exp(-z * (ct1 + 1.0));
        double cm2_0 = 1.0, cm1_0 = ct0, tc0 = 2.0 * ct0;
        double cm2_1 = 1.0, cm1_1 = ct1, tc1 = 2.0 * ct1;

        for (int k = 0; k <= MMAX; k++) {
            double ck0, ck1;
            if (k == 0)      { ck0 = 1.0; ck1 = 1.0; }
            else if (k == 1) { ck0 = ct0; ck1 = ct1; }
            else {
                ck0 = tc0 * cm1_0 - cm2_0;  cm2_0 = cm1_0;  cm1_0 = ck0;
                ck1 = tc1 * cm1_1 - cm2_1;  cm2_1 = cm1_1;  cm1_1 = ck1;
            }
            double p = f0 * ck0 + f1 * ck1;
#pragma unroll
            for (int off = 16; off; off >>= 1)
                p += __shfl_xor_sync(0xffffffffu, p, off);
            if (tid == 0) {
                double c = (2.0 / 64.0) * p;
                if (k == 0) c *= 0.5;
                s_c[k] = c;
            }
        }
        __syncwarp();
        if (tid == 0) {
            double tail = 0.0;
            int deg = 2;
            for (int k = MMAX; k >= 2; k--) {
                tail += fabs(s_c[k]);
                if (tail > 4e-5) { deg = k; break; }   // R14-verified margin
            }
            if (deg > MMAX) deg = MMAX;
            s_deg = deg;
            s_a   = (float)(4.0 / lub);
            for (int k = 0; k <= MMAX; k++) s_coef[k] = (float)s_c[k];
        }
    }
    __syncthreads();

    // ============ B2: g_offs final
    grid_barrier();
    if (lane == 0) {                      // rank own rows
        int r = atomicAdd(&g_offs[s_cntE[rl]], 1);
        g_perm[r] = erow;
    }
    // ============ B3: perm complete
    grid_barrier();

    // ============ D) phase: 16 groups of 64 threads; min-max rank pairs
    const int gi  = rl;                  // group = same 64-thread partition
    const int pgi = gi ^ 8;              // partner group (pairs i <-> 8+i)
    const int ownRank = (gi < 8) ? (blk * 8 + gi) : (NN - 1 - (blk * 8 + (gi - 8)));
    const int ownRow  = g_perm[ownRank];

    int2*  s_ellG  = reinterpret_cast<int2*>(dyn + OFF_ELL);
    float* s_ykm1  = reinterpret_cast<float*>(dyn + OFF_YKM1) + gi * DD;
    float* s_partO = reinterpret_cast<float*>(dyn + OFF_PART) + gi * DD;   // my slot
    float* s_partP = reinterpret_cast<float*>(dyn + OFF_PART) + pgi * DD;  // partner's
    float* s_o     = reinterpret_cast<float*>(dyn + OFF_O) + gi * DD;

    {
        const int c = g_cnt[ownRow];
        for (int k = lane; k < c; k += 64)
            s_ellG[gi * ELLW + k] = g_ell[(size_t)ownRow * ELLW + k];
        if (lane == 0) { s_cntG[gi] = c; s_diagG[gi] = g_diag[ownRow]; }
    }
    __syncthreads();

    const float d    = s_diagG[gi];
    const float a    = s_a;
    const int   deg  = s_deg;
    const int   cO   = s_cntG[gi];
    const int   hO   = (cO + 1) >> 1;              // own first half [0, hO)
    const int   cP   = s_cntG[pgi];
    const int   hP   = (cP + 1) >> 1;              // partner second half [hP, cP)
    const int2* lsO  = s_ellG + gi * ELLW;
    const int2* lsP  = s_ellG + pgi * ELLW + hP;
    const int   nP   = cP - hP;

    const int   ch0   = wir * 256 + (lane & 31) * 4;
    const size_t ridx0 = (((size_t)ownRow) << 9) + ch0;
    const size_t ridx1 = ridx0 + 128;

    float yk[8], acc[8];
    {
        float4 xa = f4_load(X + ridx0), xb = f4_load(X + ridx1);
        yk[0] = xa.x; yk[1] = xa.y; yk[2] = xa.z; yk[3] = xa.w;
        yk[4] = xb.x; yk[5] = xb.y; yk[6] = xb.z; yk[7] = xb.w;
    }

    // ---- init: T1 = (2/lub)*L@x - x ; o = c0*x + c1*T1
    spmv8(X, ch0, lsP, nP, 0.f, yk, acc);          // partner partial (d=0)
    f4_store(s_partP + ch0,       make_float4(acc[0], acc[1], acc[2], acc[3]));
    f4_store(s_partP + ch0 + 128, make_float4(acc[4], acc[5], acc[6], acc[7]));
    spmv8(X, ch0, lsO, hO, d, yk, acc);            // own half with diagonal
    __syncthreads();                               // partner partial ready
    {
        float4 qa = f4_load(s_partO + ch0);
        float4 qb = f4_load(s_partO + ch0 + 128);
        acc[0] += qa.x; acc[1] += qa.y; acc[2] += qa.z; acc[3] += qa.w;
        acc[4] += qb.x; acc[5] += qb.y; acc[6] += qb.z; acc[7] += qb.w;
        const float ha = 0.5f * a;
        const float c0 = s_coef[0], c1 = s_coef[1];
        float o8[8];
#pragma unroll
        for (int i = 0; i < 8; i++) {
            float t1 = ha * acc[i] - yk[i];
            o8[i] = c0 * yk[i] + c1 * t1;
            int cc = ch0 + ((i < 4) ? i : (124 + i));
            s_ykm1[cc] = yk[i];     // T0
            yk[i] = t1;             // T1
        }
        f4_store(s_o + ch0,       make_float4(o8[0], o8[1], o8[2], o8[3]));
        f4_store(s_o + ch0 + 128, make_float4(o8[4], o8[5], o8[6], o8[7]));
        f4_store(g_T1 + ridx0, make_float4(yk[0], yk[1], yk[2], yk[3]));
        f4_store(g_T1 + ridx1, make_float4(yk[4], yk[5], yk[6], yk[7]));
    }

    for (int j = 2; j <= deg; j++) {
        grid_barrier();                            // T_{j-1} globally visible
        const float* Tp = (j & 1) ? g_T2 : g_T1;
        float*       Tc = (j & 1) ? g_T1 : g_T2;

        spmv8(Tp, ch0, lsP, nP, 0.f, yk, acc);     // partner partial
        f4_store(s_partP + ch0,       make_float4(acc[0], acc[1], acc[2], acc[3]));
        f4_store(s_partP + ch0 + 128, make_float4(acc[4], acc[5], acc[6], acc[7]));
        spmv8(Tp, ch0, lsO, hO, d, yk, acc);       // own half
        __syncthreads();

        float4 qa = f4_load(s_partO + ch0);
        float4 qb = f4_load(s_partO + ch0 + 128);
        acc[0] += qa.x; acc[1] += qa.y; acc[2] += qa.z; acc[3] += qa.w;
        acc[4] += qb.x; acc[5] += qb.y; acc[6] += qb.z; acc[7] += qb.w;

        const float c = s_coef[j];
        float4 oa = f4_load(s_o + ch0);
        float4 ob = f4_load(s_o + ch0 + 128);
        float tn[8];
#pragma unroll
        for (int i = 0; i < 8; i++) {
            int cc = ch0 + ((i < 4) ? i : (124 + i));
            tn[i] = a * acc[i] - 2.f * yk[i] - s_ykm1[cc];
            if (i < 4) (&oa.x)[i]     += c * tn[i];
            else       (&ob.x)[i - 4] += c * tn[i];
            s_ykm1[cc] = yk[i];
            yk[i] = tn[i];
        }
        f4_store(s_o + ch0,       oa);
        f4_store(s_o + ch0 + 128, ob);
        if (j < deg) {                             // last T never gathered
            f4_store(Tc + ridx0, make_float4(tn[0], tn[1], tn[2], tn[3]));
            f4_store(Tc + ridx1, make_float4(tn[4], tn[5], tn[6], tn[7]));
        }
    }

    {
        float4 oa = f4_load(s_o + ch0);
        float4 ob = f4_load(s_o + ch0 + 128);
        f4_store(out + ridx0, oa);
        f4_store(out + ridx1, ob);
    }
}

// ---------------------------------------------------------------------------
extern "C" void kernel_launch(void* const* d_in, const int* in_sizes, int n_in,
                              void* d_out, int out_size) {
    const float* x = nullptr;
    const float* L = nullptr;
    const float* t = nullptr;
    for (int i = 0; i < n_in; i++) {
        if      (in_sizes[i] == NN * DD) x = (const float*)d_in[i];
        else if (in_sizes[i] == NN * NN) L = (const float*)d_in[i];
        else if (in_sizes[i] == 1)       t = (const float*)d_in[i];
    }
    float* out = (float*)d_out;

    static int smem_set = 0;
    if (!smem_set) {
        cudaFuncSetAttribute(cheb_all, cudaFuncAttributeMaxDynamicSharedMemorySize,
                             SMEM_DYN);
        smem_set = 1;
    }
    cheb_all<<<GRID, THREADS, SMEM_DYN>>>(x, L, t, out);
}